// round 11
// baseline (speedup 1.0000x reference)
#include <cuda_runtime.h>
#include <cuda_bf16.h>
#include <cstdint>

// Problem constants (fixed by the dataset shapes)
#define BB   16
#define KK   64
#define HH   160
#define WW   160
#define HWC  (HH * WW)            // 25600
#define NROWS (BB * HH)           // 2560
#define SPANS 5                   // 32-pixel spans per row (warp covers 32 px)
#define NWARPS (NROWS * SPANS)    // 12800 independent warps
#define KPT  16                   // keypoints per thread (4 g-groups)
#define NPAIR (KPT / 2)           // 8 packed k-pairs
#define NTHR 256
#define EPS_F 1e-5f

__device__ __forceinline__ float ex2_approx(float x) {
    float r; asm("ex2.approx.ftz.f32 %0, %1;" : "=f"(r) : "f"(x)); return r;
}
__device__ __forceinline__ float rcp_approx(float x) {
    float r; asm("rcp.approx.ftz.f32 %0, %1;" : "=f"(r) : "f"(x)); return r;
}
// Packed 2xfp32 (sm_100+): operands in 64-bit register pairs.
__device__ __forceinline__ uint64_t fma2(uint64_t a, uint64_t b, uint64_t c) {
    uint64_t d; asm("fma.rn.f32x2 %0, %1, %2, %3;" : "=l"(d) : "l"(a), "l"(b), "l"(c)); return d;
}
__device__ __forceinline__ uint64_t add2(uint64_t a, uint64_t b) {
    uint64_t d; asm("add.rn.f32x2 %0, %1, %2;" : "=l"(d) : "l"(a), "l"(b)); return d;
}
__device__ __forceinline__ uint64_t mul2(uint64_t a, uint64_t b) {
    uint64_t d; asm("mul.rn.f32x2 %0, %1, %2;" : "=l"(d) : "l"(a), "l"(b)); return d;
}
__device__ __forceinline__ uint64_t pack2(float lo, float hi) {
    uint64_t d; asm("mov.b64 %0, {%1, %2};" : "=l"(d) : "f"(lo), "f"(hi)); return d;
}
__device__ __forceinline__ void unpack2(uint64_t v, float& lo, float& hi) {
    asm("mov.b64 {%0, %1}, %2;" : "=f"(lo), "=f"(hi) : "l"(v));
}

// Warp-autonomous, no barriers/smem. Warp = 32 consecutive px of one row;
// lane = (qx 0..7, g 0..3); thread = 4 px x 16 k (8 packed k-pairs).
// Per STG.128 warp-op each k-plane receives a FULL 128B line from this warp
// (8 lanes x 16B contiguous) — minimal LTS transactions per byte (R7 layout).
// Along x: v(x+1)=v(x)*t(x), t(x+1)=t(x)*u -> 2 EX2 per k instead of 4.
__global__ __launch_bounds__(NTHR, 3)
void recon_conf_map_kernel(const float* __restrict__ kp,    // [B,K,2]
                           const float* __restrict__ psx,
                           const float* __restrict__ psy,
                           const float* __restrict__ prho,
                           float* __restrict__ out)         // [B,K,H,W]
{
    const int t    = blockIdx.x * NTHR + threadIdx.x;
    const int w    = t >> 5;
    const int lane = t & 31;
    const int row  = w / SPANS;              // b*HH + y
    const int span = w - row * SPANS;
    const int b    = row / HH;
    const int y    = row - b * HH;

    const int qx = lane & 7;                 // 0..7: x-quad within 32-px span
    const int g  = lane >> 3;                // 0..3: k-group
    const int kbase = g * KPT;

    // Scalars (broadcast LDG, L1-cached)
    const float sx  = psx[0];
    const float sy  = psy[0];
    const float rho = prho[0];

    const float omr2 = 1.0f - rho * rho;
    const float num1 = -0.5f / omr2;
    const float L2E  = 1.4426950408889634f;
    const float den  = 1.0f / (6.2831853071795864f * sx * sy * sqrtf(omr2));
    const float l2den = log2f(den);

    // base-2 exponent e(x) = Bq*x^2 + q1*x + q0 per (k,row)
    const float A  = num1 * L2E / (sy * sy);
    const float Bq = num1 * L2E / (sx * sx);
    const float C  = num1 * L2E * (-2.0f * rho) / (sx * sy);

    const float fx0 = (float)(span * 32 + qx * 4);
    const float fy  = (float)y;

    // Packed broadcast constants
    const uint64_t Ap    = pack2(A, A);
    const uint64_t Bqp   = pack2(Bq, Bq);
    const uint64_t Cp    = pack2(C, C);
    const uint64_t Cnp   = pack2(-C, -C);
    const uint64_t nBq2p = pack2(-2.0f * Bq, -2.0f * Bq);
    const uint64_t l2dp  = pack2(l2den, l2den);
    const uint64_t fyp   = pack2(fy, fy);
    const uint64_t neg1p = pack2(-1.0f, -1.0f);
    const uint64_t f0p   = pack2(fx0, fx0);
    const uint64_t p0p   = pack2(Bq * fx0 * fx0, Bq * fx0 * fx0);
    const float    rb    = Bq * (2.0f * fx0 + 1.0f);   // ratio exponent at x=fx0
    const uint64_t rbp   = pack2(rb, rb);
    const float    u     = ex2_approx(2.0f * Bq);      // per-step ratio of ratios
    const uint64_t up    = pack2(u, u);

    // keypoints for this thread's 16 k: 8 float4 loads (kx_a,ky_a,kx_b,ky_b)
    const float4* __restrict__ kpp4 =
        reinterpret_cast<const float4*>(kp + 2 * (b * KK + kbase));

    uint64_t vs[NPAIR][4];
    uint64_t acc0 = 0, acc1 = 0, acc2 = 0, acc3 = 0;  // packed (+0,+0)

#pragma unroll
    for (int j = 0; j < NPAIR; ++j) {
        const float4 kk = kpp4[j];
        const uint64_t kxp = pack2(kk.x, kk.z);
        const uint64_t kyp = pack2(kk.y, kk.w);
        // coefficients (packed over the k-pair):
        //   dy = fy - ky; cy = C*dy; ay = A*dy^2 + l2den
        //   q1 = -2Bq*kx + cy;  q0 = kx*(Bq*kx - cy) + ay
        const uint64_t dyp  = fma2(kyp, neg1p, fyp);
        const uint64_t cyp  = mul2(Cp,  dyp);
        const uint64_t cynp = mul2(Cnp, dyp);
        const uint64_t ayp  = fma2(mul2(Ap, dyp), dyp, l2dp);
        const uint64_t q1p  = fma2(nBq2p, kxp, cyp);
        const uint64_t q0p  = fma2(kxp, fma2(Bqp, kxp, cynp), ayp);

        // seed value and ratio at x = fx0
        const uint64_t e0p  = add2(fma2(q1p, f0p, p0p), q0p);
        const uint64_t t0ep = add2(q1p, rbp);
        float ea, eb, ta, tb;
        unpack2(e0p,  ea, eb);
        unpack2(t0ep, ta, tb);
        const uint64_t v0p = pack2(ex2_approx(ea), ex2_approx(eb));
        const uint64_t t0p = pack2(ex2_approx(ta), ex2_approx(tb));

        // geometric chain across the 4 pixels
        const uint64_t v1p = mul2(v0p, t0p);
        const uint64_t t1p = mul2(t0p, up);
        const uint64_t v2p = mul2(v1p, t1p);
        const uint64_t t2p = mul2(t1p, up);
        const uint64_t v3p = mul2(v2p, t2p);

        vs[j][0] = v0p; vs[j][1] = v1p; vs[j][2] = v2p; vs[j][3] = v3p;
        acc0 = add2(acc0, v0p);
        acc1 = add2(acc1, v1p);
        acc2 = add2(acc2, v2p);
        acc3 = add2(acc3, v3p);
    }

    // collapse packed halves, then butterfly over the 4 g-groups (lane bits 3,4)
    float s0, s1, s2, s3, hx;
    unpack2(acc0, s0, hx); s0 += hx;
    unpack2(acc1, s1, hx); s1 += hx;
    unpack2(acc2, s2, hx); s2 += hx;
    unpack2(acc3, s3, hx); s3 += hx;
#pragma unroll
    for (int m = 8; m < 32; m <<= 1) {
        s0 += __shfl_xor_sync(0xffffffffu, s0, m);
        s1 += __shfl_xor_sync(0xffffffffu, s1, m);
        s2 += __shfl_xor_sync(0xffffffffu, s2, m);
        s3 += __shfl_xor_sync(0xffffffffu, s3, m);
    }
    const float i0 = rcp_approx(s0 + EPS_F);
    const float i1 = rcp_approx(s1 + EPS_F);
    const float i2 = rcp_approx(s2 + EPS_F);
    const float i3 = rcp_approx(s3 + EPS_F);
    const uint64_t i0p = pack2(i0, i0);
    const uint64_t i1p = pack2(i1, i1);
    const uint64_t i2p = pack2(i2, i2);
    const uint64_t i3p = pack2(i3, i3);

    // Stores: per STG.128 warp-op each of 4 k-planes gets a FULL 128B line
    // (8 lanes x 16B contiguous, 128B-aligned).
    float4* __restrict__ o = reinterpret_cast<float4*>(
        out + ((size_t)b * KK + kbase) * HWC + (size_t)y * WW) + (span * 8 + qx);
#pragma unroll
    for (int j = 0; j < NPAIR; ++j) {
        const uint64_t r0 = mul2(vs[j][0], i0p);
        const uint64_t r1 = mul2(vs[j][1], i1p);
        const uint64_t r2 = mul2(vs[j][2], i2p);
        const uint64_t r3 = mul2(vs[j][3], i3p);
        float4 va, vb;                        // lo/hi halves are free reg names
        unpack2(r0, va.x, vb.x);
        unpack2(r1, va.y, vb.y);
        unpack2(r2, va.z, vb.z);
        unpack2(r3, va.w, vb.w);
        o[(size_t)(2 * j)     * (HWC / 4)] = va;
        o[(size_t)(2 * j + 1) * (HWC / 4)] = vb;
    }
}

extern "C" void kernel_launch(void* const* d_in, const int* in_sizes, int n_in,
                              void* d_out, int out_size) {
    // metadata order: keypoints, std_x, std_y, correlation, DetectionMap (unused)
    const float* kp   = (const float*)d_in[0];
    const float* psx  = (const float*)d_in[1];
    const float* psy  = (const float*)d_in[2];
    const float* prho = (const float*)d_in[3];
    float* out = (float*)d_out;

    const int total_threads = NWARPS * 32;            // 409600
    recon_conf_map_kernel<<<total_threads / NTHR, NTHR>>>(kp, psx, psy, prho, out);
}